// round 14
// baseline (speedup 1.0000x reference)
#include <cuda_runtime.h>
#include <cuda_fp16.h>
#include <math.h>

#define N_NODES 50000
#define N_PAD   50048           // 391 * 128
#define N_EDGES 640000
#define IN_DIM 5
#define HID 128
#define NUM_GRAPHS 512
#define NB 196                  // scan blocks: 196*256 >= N_NODES

// ---------------- device scratch (static, no allocation) ----------------
// cat layout per node: 256 fp16 cols. Layer0 h lives at cols [128:256].
// k_gg<0> reads h@128, writes its output h@0. k_gg<1> reads h@0.
__device__ __align__(16) __half g_cath[(size_t)N_PAD * 256];
__device__ __align__(16) __half g_catl[(size_t)N_PAD * 256];
__device__ __align__(16) __half g_W1hi[256 * HID], g_W1lo[256 * HID];
__device__ __align__(16) __half g_W2hi[256 * HID], g_W2lo[256 * HID];
__device__ float g_pooled[NUM_GRAPHS * HID];
__device__ int   g_deg   [N_NODES];
__device__ int   g_rowptr[N_NODES + 1];
__device__ int   g_cursor[N_NODES];
__device__ int   g_csr_src[N_EDGES];
__device__ int   g_cnt   [NUM_GRAPHS];
__device__ int   g_blksum[NB];

// split helpers
__device__ __forceinline__ void split2(float v0, float v1, unsigned& hi, unsigned& lo) {
    __half2 h = __floats2half2_rn(v0, v1);
    float2 hf = __half22float2(h);
    __half2 l = __floats2half2_rn(v0 - hf.x, v1 - hf.y);
    hi = *(unsigned*)&h;
    lo = *(unsigned*)&l;
}

// ---------------- init: zero + weight hi/lo conversion (merged) -------------
__global__ void k_init(const float* __restrict__ Wrel1, const float* __restrict__ Wroot1,
                       const float* __restrict__ Wrel2, const float* __restrict__ Wroot2) {
    int i = blockIdx.x * blockDim.x + threadIdx.x;    // 0..65535
    if (i < N_NODES) g_deg[i] = 0;
    if (i < NUM_GRAPHS * HID) g_pooled[i] = 0.0f;
    if (i < NUM_GRAPHS) g_cnt[i] = 0;
    if (i < (N_PAD - N_NODES) * 256 / 2) {            // 48 pad rows as uint
        ((unsigned*)(g_cath + (size_t)N_NODES * 256))[i] = 0u;
        ((unsigned*)(g_catl + (size_t)N_NODES * 256))[i] = 0u;
    }
    if (i < 2 * 256 * HID) {
        int layer = i >> 15;
        int j = i & 32767;
        int r = j >> 7, c = j & 127;
        const float* Wr = layer ? Wrel2 : Wrel1;
        const float* Wo = layer ? Wroot2 : Wroot1;
        float v = (r < 128) ? Wr[r * HID + c] : Wo[(r - 128) * HID + c];
        __half hi = __float2half_rn(v);
        __half lo = __float2half_rn(v - __half2float(hi));
        if (layer) { g_W2hi[j] = hi; g_W2lo[j] = lo; }
        else       { g_W1hi[j] = hi; g_W1lo[j] = lo; }
    }
}

// ---------------- CSR build ----------------
__global__ void k_histcnt(const int* __restrict__ ei, const int* __restrict__ batch) {
    int e = blockIdx.x * blockDim.x + threadIdx.x;
    if (e < N_EDGES) atomicAdd(&g_deg[ei[N_EDGES + e]], 1);
    if (e < N_NODES) atomicAdd(&g_cnt[batch[e]], 1);
}

__global__ void k_scanA() {
    __shared__ int red[256];
    int t = blockIdx.x * 256 + threadIdx.x;
    int d = (t < N_NODES) ? g_deg[t] : 0;
    red[threadIdx.x] = d;
    __syncthreads();
#pragma unroll
    for (int off = 128; off > 0; off >>= 1) {
        if (threadIdx.x < off) red[threadIdx.x] += red[threadIdx.x + off];
        __syncthreads();
    }
    if (threadIdx.x == 0) g_blksum[blockIdx.x] = red[0];
}

// scanC with block-sum scan folded in (every block redundantly scans g_blksum)
__global__ void k_scanC() {
    __shared__ int bs[256];
    __shared__ int s[256];
    int tt = threadIdx.x;
    int bv = (tt < NB) ? g_blksum[tt] : 0;
    bs[tt] = bv;
    __syncthreads();
#pragma unroll
    for (int off = 1; off < 256; off <<= 1) {
        int u = (tt >= off) ? bs[tt - off] : 0;
        __syncthreads();
        bs[tt] += u;
        __syncthreads();
    }
    int blkoff = (blockIdx.x == 0) ? 0 : bs[blockIdx.x - 1];

    int t = blockIdx.x * 256 + tt;
    int d = (t < N_NODES) ? g_deg[t] : 0;
    s[tt] = d;
    __syncthreads();
#pragma unroll
    for (int off = 1; off < 256; off <<= 1) {
        int u = (tt >= off) ? s[tt - off] : 0;
        __syncthreads();
        s[tt] += u;
        __syncthreads();
    }
    int excl = s[tt] - d + blkoff;
    if (t < N_NODES) {
        g_rowptr[t] = excl;
        g_cursor[t] = excl;
    }
    if (blockIdx.x == 0 && tt == 0) g_rowptr[N_NODES] = bs[NB - 1];
}

__global__ void k_scatter(const int* __restrict__ ei) {
    int e = blockIdx.x * blockDim.x + threadIdx.x;
    if (e < N_EDGES) {
        int d = ei[N_EDGES + e];
        int p = atomicAdd(&g_cursor[d], 1);
        g_csr_src[p] = ei[e];
    }
}

// ---------------- layer 0 fused: agg + linear + relu, warp per node --------
__global__ __launch_bounds__(256)
void k_l0(const float* __restrict__ x,
          const float* __restrict__ Wrel, const float* __restrict__ brel,
          const float* __restrict__ Wroot) {
    int node = (blockIdx.x * blockDim.x + threadIdx.x) >> 5;
    int lane = threadIdx.x & 31;
    if (node >= N_NODES) return;

    float s[IN_DIM];
#pragma unroll
    for (int k = 0; k < IN_DIM; k++) s[k] = 0.0f;

    int beg = g_rowptr[node], end = g_rowptr[node + 1];
    for (int j = beg + lane; j < end; j += 32) {
        const float* xr = x + (size_t)g_csr_src[j] * IN_DIM;
#pragma unroll
        for (int k = 0; k < IN_DIM; k++) s[k] += __ldg(xr + k);
    }
#pragma unroll
    for (int k = 0; k < IN_DIM; k++) {
#pragma unroll
        for (int off = 16; off > 0; off >>= 1)
            s[k] += __shfl_xor_sync(0xffffffffu, s[k], off);
    }

    float sx[IN_DIM];
#pragma unroll
    for (int k = 0; k < IN_DIM; k++) sx[k] = __ldg(&x[(size_t)node * IN_DIM + k]);

    int c0 = lane * 4;
    float4 v = *(const float4*)(brel + c0);
#pragma unroll
    for (int k = 0; k < IN_DIM; k++) {
        float4 wr = *(const float4*)(Wrel + k * HID + c0);
        float4 wo = *(const float4*)(Wroot + k * HID + c0);
        v.x = fmaf(s[k], wr.x, fmaf(sx[k], wo.x, v.x));
        v.y = fmaf(s[k], wr.y, fmaf(sx[k], wo.y, v.y));
        v.z = fmaf(s[k], wr.z, fmaf(sx[k], wo.z, v.z));
        v.w = fmaf(s[k], wr.w, fmaf(sx[k], wo.w, v.w));
    }
    v.x = fmaxf(v.x, 0.f); v.y = fmaxf(v.y, 0.f);
    v.z = fmaxf(v.z, 0.f); v.w = fmaxf(v.w, 0.f);

    unsigned h01, l01, h23, l23;
    split2(v.x, v.y, h01, l01);
    split2(v.z, v.w, h23, l23);
    *(uint2*)(g_cath + (size_t)node * 256 + 128 + c0) = make_uint2(h01, h23);
    *(uint2*)(g_catl + (size_t)node * 256 + 128 + c0) = make_uint2(l01, l23);
}

// ---------------- fused gather + split-fp16 tensor-core GEMM ---------------
__device__ __forceinline__ void mma16816(float* c, const unsigned* a,
                                         unsigned b0, unsigned b1) {
    asm volatile("mma.sync.aligned.m16n8k16.row.col.f32.f16.f16.f32 "
                 "{%0,%1,%2,%3}, {%4,%5,%6,%7}, {%8,%9}, {%0,%1,%2,%3};"
                 : "+f"(c[0]), "+f"(c[1]), "+f"(c[2]), "+f"(c[3])
                 : "r"(a[0]), "r"(a[1]), "r"(a[2]), "r"(a[3]), "r"(b0), "r"(b1));
}

#define LDMX4(dst, ptr)                                                          \
    { unsigned _ad = (unsigned)__cvta_generic_to_shared(ptr);                    \
      asm volatile("ldmatrix.sync.aligned.m8n8.x4.shared.b16 {%0,%1,%2,%3}, [%4];" \
                   : "=r"(dst[0]), "=r"(dst[1]), "=r"(dst[2]), "=r"(dst[3]) : "r"(_ad)); }
#define LDMX4T(dst, ptr)                                                         \
    { unsigned _ad = (unsigned)__cvta_generic_to_shared(ptr);                    \
      asm volatile("ldmatrix.sync.aligned.m8n8.x4.trans.shared.b16 {%0,%1,%2,%3}, [%4];" \
                   : "=r"(dst[0]), "=r"(dst[1]), "=r"(dst[2]), "=r"(dst[3]) : "r"(_ad)); }

__device__ __forceinline__ void cpa16(void* smem_dst, const void* gsrc) {
    unsigned d = (unsigned)__cvta_generic_to_shared(smem_dst);
    asm volatile("cp.async.cg.shared.global [%0], [%1], 16;" :: "r"(d), "l"(gsrc));
}
#define CP_COMMIT() asm volatile("cp.async.commit_group;")

struct GGSmem {
    __half Aah[128][136];       // agg hi (cols 0..127 used)
    __half Aal[128][136];       // agg lo
    __half Hhs[2][128][24];     // h-chunk stream hi
    __half Hls[2][128][24];     // h-chunk stream lo
    __half Whs[2][16][136];     // W chunk hi
    __half Wls[2][16][136];     // W chunk lo
};                              // 111616 bytes

// Block: 128 nodes, 256 threads (8 warps; warp grid 4x2 for the GEMM).
// POOL==0: h in @ col 128, out h @ col 0, weights W1, relu.
// POOL==1: h in @ col 0, pool via atomicAdd, weights W2.
template <int POOL>
__global__ __launch_bounds__(256, 2)
void k_gg(const float* __restrict__ bias, const int* __restrict__ batch) {
    extern __shared__ char smem_raw[];
    GGSmem& S = *reinterpret_cast<GGSmem*>(smem_raw);

    const __half* __restrict__ WH = POOL ? g_W2hi : g_W1hi;
    const __half* __restrict__ WL = POOL ? g_W2lo : g_W1lo;
    const int HIN  = POOL ? 0 : 128;   // h input column offset
    const int HOUT = 0;                // k_gg<0> output column offset

    const int tid = threadIdx.x;
    const int lane = tid & 31;
    const int w = tid >> 5;
    const int wr = w >> 1;            // 0..3 : rows wr*32 .. +32
    const int wc = w & 1;             // 0..1 : cols wc*64 .. +64
    const int row0 = blockIdx.x * 128;

    // per-thread cp.async coordinates
    const int a_r = tid >> 1, a_c = (tid & 1) * 8;        // H: 128 rows x 2 segs
    const int w_r = tid >> 4, w_c = (tid & 15) * 8;       // W: 16 rows x 16 segs

    // prologue: W chunk 0 in flight during gather
    cpa16(&S.Whs[0][w_r][w_c], WH + (size_t)w_r * HID + w_c);
    cpa16(&S.Wls[0][w_r][w_c], WL + (size_t)w_r * HID + w_c);
    CP_COMMIT();

    // ---- phase 1: gather (warp per node, 16 nodes per warp) ----
    for (int i = 0; i < 16; i++) {
        int node = row0 + w * 16 + i;
        float a0 = 0.f, a1 = 0.f, a2 = 0.f, a3 = 0.f;
        if (node < N_NODES) {
            int beg = g_rowptr[node], end = g_rowptr[node + 1];
            int j = beg;
            for (; j + 3 < end; j += 4) {
                int s0 = g_csr_src[j], s1 = g_csr_src[j + 1];
                int s2 = g_csr_src[j + 2], s3 = g_csr_src[j + 3];
                uint2 p0 = __ldg((const uint2*)(g_cath + (size_t)s0 * 256 + HIN) + lane);
                uint2 p1 = __ldg((const uint2*)(g_cath + (size_t)s1 * 256 + HIN) + lane);
                uint2 p2 = __ldg((const uint2*)(g_cath + (size_t)s2 * 256 + HIN) + lane);
                uint2 p3 = __ldg((const uint2*)(g_cath + (size_t)s3 * 256 + HIN) + lane);
                float2 f0 = __half22float2(*(__half2*)&p0.x);
                float2 f1 = __half22float2(*(__half2*)&p0.y);
                float2 g0 = __half22float2(*(__half2*)&p1.x);
                float2 g1 = __half22float2(*(__half2*)&p1.y);
                float2 q0 = __half22float2(*(__half2*)&p2.x);
                float2 q1 = __half22float2(*(__half2*)&p2.y);
                float2 r0 = __half22float2(*(__half2*)&p3.x);
                float2 r1 = __half22float2(*(__half2*)&p3.y);
                a0 += (f0.x + g0.x) + (q0.x + r0.x);
                a1 += (f0.y + g0.y) + (q0.y + r0.y);
                a2 += (f1.x + g1.x) + (q1.x + r1.x);
                a3 += (f1.y + g1.y) + (q1.y + r1.y);
            }
            for (; j < end; j++) {
                int s0 = g_csr_src[j];
                uint2 p0 = __ldg((const uint2*)(g_cath + (size_t)s0 * 256 + HIN) + lane);
                float2 f0 = __half22float2(*(__half2*)&p0.x);
                float2 f1 = __half22float2(*(__half2*)&p0.y);
                a0 += f0.x; a1 += f0.y; a2 += f1.x; a3 += f1.y;
            }
        }
        unsigned h01, l01, h23, l23;
        split2(a0, a1, h01, l01);
        split2(a2, a3, h23, l23);
        *(uint2*)&S.Aah[w * 16 + i][lane * 4] = make_uint2(h01, h23);
        *(uint2*)&S.Aal[w * 16 + i][lane * 4] = make_uint2(l01, l23);
    }

    // ---- phase 2: GEMM over K=256 (16 chunks of 16) ----
    float c[2][8][4];
#pragma unroll
    for (int i = 0; i < 2; i++)
#pragma unroll
        for (int t = 0; t < 8; t++)
#pragma unroll
            for (int q = 0; q < 4; q++) c[i][t][q] = 0.0f;

    const int a_co = (lane >> 4) << 3;
    const int b_kr = (lane & 7) + (((lane >> 3) & 1) << 3);
    const int b_no = (lane >> 4) << 3;

    for (int kc = 0; kc < 16; kc++) {
        const int buf = kc & 1;
        if (kc + 1 < 16) {
            const int nb = (kc + 1) & 1;
            const int k0 = (kc + 1) * 16;
            cpa16(&S.Whs[nb][w_r][w_c], WH + (size_t)(k0 + w_r) * HID + w_c);
            cpa16(&S.Wls[nb][w_r][w_c], WL + (size_t)(k0 + w_r) * HID + w_c);
            if (kc + 1 >= 8) {   // h chunk for kc+1
                const int hk = (kc + 1 - 8) * 16;
                cpa16(&S.Hhs[nb][a_r][a_c],
                      g_cath + (size_t)(row0 + a_r) * 256 + HIN + hk + a_c);
                cpa16(&S.Hls[nb][a_r][a_c],
                      g_catl + (size_t)(row0 + a_r) * 256 + HIN + hk + a_c);
            }
            CP_COMMIT();
            asm volatile("cp.async.wait_group 1;");
        } else {
            asm volatile("cp.async.wait_group 0;");
        }
        __syncthreads();   // covers gather completion (kc=0) + buffer readiness

        unsigned ah0[4], al0[4], ah1[4], al1[4];
        if (kc < 8) {
            const int col = kc * 16 + a_co;
            LDMX4(ah0, &S.Aah[wr * 32 + (lane & 15)][col]);
            LDMX4(al0, &S.Aal[wr * 32 + (lane & 15)][col]);
            LDMX4(ah1, &S.Aah[wr * 32 + 16 + (lane & 15)][col]);
            LDMX4(al1, &S.Aal[wr * 32 + 16 + (lane & 15)][col]);
        } else {
            LDMX4(ah0, &S.Hhs[buf][wr * 32 + (lane & 15)][a_co]);
            LDMX4(al0, &S.Hls[buf][wr * 32 + (lane & 15)][a_co]);
            LDMX4(ah1, &S.Hhs[buf][wr * 32 + 16 + (lane & 15)][a_co]);
            LDMX4(al1, &S.Hls[buf][wr * 32 + 16 + (lane & 15)][a_co]);
        }
#pragma unroll
        for (int t = 0; t < 4; t++) {
            unsigned bh[4], bl[4];
            LDMX4T(bh, &S.Whs[buf][b_kr][wc * 64 + t * 16 + b_no]);
            LDMX4T(bl, &S.Wls[buf][b_kr][wc * 64 + t * 16 + b_no]);
            mma16816(c[0][2 * t],     ah0, bh[0], bh[1]);
            mma16816(c[0][2 * t],     ah0, bl[0], bl[1]);
            mma16816(c[0][2 * t],     al0, bh[0], bh[1]);
            mma16816(c[0][2 * t + 1], ah0, bh[2], bh[3]);
            mma16816(c[0][2 * t + 1], ah0, bl[2], bl[3]);
            mma16816(c[0][2 * t + 1], al0, bh[2], bh[3]);
            mma16816(c[1][2 * t],     ah1, bh[0], bh[1]);
            mma16816(c[1][2 * t],     ah1, bl[0], bl[1]);
            mma16816(c[1][2 * t],     al1, bh[0], bh[1]);
            mma16816(c[1][2 * t + 1], ah1, bh[2], bh[3]);
            mma16816(c[1][2 * t + 1], ah1, bl[2], bl[3]);
            mma16816(c[1][2 * t + 1], al1, bh[2], bh[3]);
        }
        __syncthreads();
    }

    // ---- epilogue ----
#pragma unroll
    for (int rf = 0; rf < 2; rf++) {
        int r0 = row0 + wr * 32 + rf * 16 + (lane >> 2);
        int r1 = r0 + 8;
        int g0 = 0, g1 = 0;
        if (POOL) {
            g0 = (r0 < N_NODES) ? batch[r0] : 0;
            g1 = (r1 < N_NODES) ? batch[r1] : 0;
        }
#pragma unroll
        for (int t2 = 0; t2 < 8; t2++) {
            int col = wc * 64 + t2 * 8 + (lane & 3) * 2;
            float bv0 = bias[col], bv1 = bias[col + 1];
            float v00 = c[rf][t2][0] + bv0, v01 = c[rf][t2][1] + bv1;
            float v10 = c[rf][t2][2] + bv0, v11 = c[rf][t2][3] + bv1;
            if (!POOL) {
                v00 = fmaxf(v00, 0.f); v01 = fmaxf(v01, 0.f);
                v10 = fmaxf(v10, 0.f); v11 = fmaxf(v11, 0.f);
                unsigned h0v, l0v, h1v, l1v;
                split2(v00, v01, h0v, l0v);
                split2(v10, v11, h1v, l1v);
                *(unsigned*)(g_cath + (size_t)r0 * 256 + HOUT + col) = h0v;
                *(unsigned*)(g_catl + (size_t)r0 * 256 + HOUT + col) = l0v;
                *(unsigned*)(g_cath + (size_t)r1 * 256 + HOUT + col) = h1v;
                *(unsigned*)(g_catl + (size_t)r1 * 256 + HOUT + col) = l1v;
            } else {
                if (r0 < N_NODES) {
                    atomicAdd(&g_pooled[(size_t)g0 * HID + col], v00);
                    atomicAdd(&g_pooled[(size_t)g0 * HID + col + 1], v01);
                }
                if (r1 < N_NODES) {
                    atomicAdd(&g_pooled[(size_t)g1 * HID + col], v10);
                    atomicAdd(&g_pooled[(size_t)g1 * HID + col + 1], v11);
                }
            }
        }
    }
}

// ---------------- final: mean pool -> linear -> sigmoid ----------------
__global__ void k_final(const float* __restrict__ Wlin, const float* __restrict__ blin,
                        float* __restrict__ out) {
    int g = blockIdx.x;
    int t = threadIdx.x;              // 128
    float cnt = fmaxf((float)g_cnt[g], 1.0f);
    float v = g_pooled[(size_t)g * HID + t] * (1.0f / cnt) * Wlin[t];
#pragma unroll
    for (int off = 16; off > 0; off >>= 1)
        v += __shfl_xor_sync(0xffffffffu, v, off);
    __shared__ float ws[4];
    if ((t & 31) == 0) ws[t >> 5] = v;
    __syncthreads();
    if (t == 0) {
        float s = ws[0] + ws[1] + ws[2] + ws[3] + blin[0];
        out[g] = 1.0f / (1.0f + expf(-s));
    }
}

// ---------------- launch ----------------
extern "C" void kernel_launch(void* const* d_in, const int* in_sizes, int n_in,
                              void* d_out, int out_size) {
    const float* x      = (const float*)d_in[0];
    const int*   ei     = (const int*)d_in[1];
    const int*   batch  = (const int*)d_in[2];
    const float* Wrel0  = (const float*)d_in[3];
    const float* brel0  = (const float*)d_in[4];
    const float* Wroot0 = (const float*)d_in[5];
    const float* Wrel1  = (const float*)d_in[6];
    const float* brel1  = (const float*)d_in[7];
    const float* Wroot1 = (const float*)d_in[8];
    const float* Wrel2  = (const float*)d_in[9];
    const float* brel2  = (const float*)d_in[10];
    const float* Wroot2 = (const float*)d_in[11];
    const float* Wlin   = (const float*)d_in[12];
    const float* blin   = (const float*)d_in[13];
    float* out = (float*)d_out;

    static bool attr_done = false;
    if (!attr_done) {
        cudaFuncSetAttribute(k_gg<0>, cudaFuncAttributeMaxDynamicSharedMemorySize,
                             (int)sizeof(GGSmem));
        cudaFuncSetAttribute(k_gg<1>, cudaFuncAttributeMaxDynamicSharedMemorySize,
                             (int)sizeof(GGSmem));
        attr_done = true;
    }

    k_init<<<256, 256>>>(Wrel1, Wroot1, Wrel2, Wroot2);
    k_histcnt<<<(N_EDGES + 255) / 256, 256>>>(ei, batch);
    k_scanA<<<NB, 256>>>();
    k_scanC<<<NB, 256>>>();
    k_scatter<<<(N_EDGES + 255) / 256, 256>>>(ei);

    // layer 0 (fused agg + linear + relu) -> h @ col 128
    k_l0<<<(N_NODES * 32 + 255) / 256, 256>>>(x, Wrel0, brel0, Wroot0);

    // layer 1: fused gather + GEMM (reads h@128, writes h@0)
    k_gg<0><<<N_PAD / 128, 256, sizeof(GGSmem)>>>(brel1, batch);

    // layer 2: fused gather + GEMM + pooling (reads h@0)
    k_gg<1><<<N_PAD / 128, 256, sizeof(GGSmem)>>>(brel2, batch);

    // head
    k_final<<<NUM_GRAPHS, HID>>>(Wlin, blin, out);
}

// round 15
// speedup vs baseline: 1.2919x; 1.2919x over previous
#include <cuda_runtime.h>
#include <cuda_fp16.h>
#include <math.h>

#define N_NODES 50000
#define N_PAD   50048           // 391 * 128
#define N_EDGES 640000
#define IN_DIM 5
#define HID 128
#define NUM_GRAPHS 512
#define NB 196                  // scan blocks: 196*256 >= N_NODES

// ---------------- device scratch (static, no allocation) ----------------
// cat[n][0:128] = agg, cat[n][128:256] = h ; hi/lo fp16 split (hi+lo ~= fp32)
__device__ __align__(16) __half g_cath[(size_t)N_PAD * 256];
__device__ __align__(16) __half g_catl[(size_t)N_PAD * 256];
__device__ __align__(16) __half g_W1hi[256 * HID], g_W1lo[256 * HID];
__device__ __align__(16) __half g_W2hi[256 * HID], g_W2lo[256 * HID];
__device__ float g_pooled[NUM_GRAPHS * HID];
__device__ int   g_deg   [N_NODES];
__device__ int   g_rowptr[N_NODES + 1];
__device__ int   g_cursor[N_NODES];
__device__ int   g_csr_src[N_EDGES];
__device__ int   g_cnt   [NUM_GRAPHS];
__device__ int   g_blksum[NB];

// split helpers
__device__ __forceinline__ void split2(float v0, float v1, unsigned& hi, unsigned& lo) {
    __half2 h = __floats2half2_rn(v0, v1);
    float2 hf = __half22float2(h);
    __half2 l = __floats2half2_rn(v0 - hf.x, v1 - hf.y);
    hi = *(unsigned*)&h;
    lo = *(unsigned*)&l;
}

// ---------------- init: zero + weight hi/lo conversion (merged) -------------
__global__ void k_init(const float* __restrict__ Wrel1, const float* __restrict__ Wroot1,
                       const float* __restrict__ Wrel2, const float* __restrict__ Wroot2) {
    int i = blockIdx.x * blockDim.x + threadIdx.x;    // 0..65535
    if (i < N_NODES) g_deg[i] = 0;
    if (i < NUM_GRAPHS * HID) g_pooled[i] = 0.0f;
    if (i < NUM_GRAPHS) g_cnt[i] = 0;
    if (i < (N_PAD - N_NODES) * 256 / 2) {            // 48 pad rows as uint
        ((unsigned*)(g_cath + (size_t)N_NODES * 256))[i] = 0u;
        ((unsigned*)(g_catl + (size_t)N_NODES * 256))[i] = 0u;
    }
    if (i < 2 * 256 * HID) {
        int layer = i >> 15;
        int j = i & 32767;
        int r = j >> 7, c = j & 127;
        const float* Wr = layer ? Wrel2 : Wrel1;
        const float* Wo = layer ? Wroot2 : Wroot1;
        float v = (r < 128) ? Wr[r * HID + c] : Wo[(r - 128) * HID + c];
        __half hi = __float2half_rn(v);
        __half lo = __float2half_rn(v - __half2float(hi));
        if (layer) { g_W2hi[j] = hi; g_W2lo[j] = lo; }
        else       { g_W1hi[j] = hi; g_W1lo[j] = lo; }
    }
}

// ---------------- CSR build ----------------
__global__ void k_histcnt(const int* __restrict__ ei, const int* __restrict__ batch) {
    int e = blockIdx.x * blockDim.x + threadIdx.x;
    if (e < N_EDGES) atomicAdd(&g_deg[ei[N_EDGES + e]], 1);
    if (e < N_NODES) atomicAdd(&g_cnt[batch[e]], 1);
}

__global__ void k_scanA() {
    __shared__ int red[256];
    int t = blockIdx.x * 256 + threadIdx.x;
    int d = (t < N_NODES) ? g_deg[t] : 0;
    red[threadIdx.x] = d;
    __syncthreads();
#pragma unroll
    for (int off = 128; off > 0; off >>= 1) {
        if (threadIdx.x < off) red[threadIdx.x] += red[threadIdx.x + off];
        __syncthreads();
    }
    if (threadIdx.x == 0) g_blksum[blockIdx.x] = red[0];
}

// scanC with block-sum scan folded in (every block redundantly scans g_blksum)
__global__ void k_scanC() {
    __shared__ int bs[256];
    __shared__ int s[256];
    int tt = threadIdx.x;
    int bv = (tt < NB) ? g_blksum[tt] : 0;
    bs[tt] = bv;
    __syncthreads();
#pragma unroll
    for (int off = 1; off < 256; off <<= 1) {
        int u = (tt >= off) ? bs[tt - off] : 0;
        __syncthreads();
        bs[tt] += u;
        __syncthreads();
    }
    int blkoff = (blockIdx.x == 0) ? 0 : bs[blockIdx.x - 1];

    int t = blockIdx.x * 256 + tt;
    int d = (t < N_NODES) ? g_deg[t] : 0;
    s[tt] = d;
    __syncthreads();
#pragma unroll
    for (int off = 1; off < 256; off <<= 1) {
        int u = (tt >= off) ? s[tt - off] : 0;
        __syncthreads();
        s[tt] += u;
        __syncthreads();
    }
    int excl = s[tt] - d + blkoff;
    if (t < N_NODES) {
        g_rowptr[t] = excl;
        g_cursor[t] = excl;
    }
    if (blockIdx.x == 0 && tt == 0) g_rowptr[N_NODES] = bs[NB - 1];
}

__global__ void k_scatter(const int* __restrict__ ei) {
    int e = blockIdx.x * blockDim.x + threadIdx.x;
    if (e < N_EDGES) {
        int d = ei[N_EDGES + e];
        int p = atomicAdd(&g_cursor[d], 1);
        g_csr_src[p] = ei[e];
    }
}

// ---------------- layer 0 fused: agg + linear + relu, warp per node --------
__global__ __launch_bounds__(256)
void k_l0(const float* __restrict__ x,
          const float* __restrict__ Wrel, const float* __restrict__ brel,
          const float* __restrict__ Wroot) {
    int node = (blockIdx.x * blockDim.x + threadIdx.x) >> 5;
    int lane = threadIdx.x & 31;
    if (node >= N_NODES) return;

    float s[IN_DIM];
#pragma unroll
    for (int k = 0; k < IN_DIM; k++) s[k] = 0.0f;

    int beg = g_rowptr[node], end = g_rowptr[node + 1];
    for (int j = beg + lane; j < end; j += 32) {
        const float* xr = x + (size_t)g_csr_src[j] * IN_DIM;
#pragma unroll
        for (int k = 0; k < IN_DIM; k++) s[k] += __ldg(xr + k);
    }
#pragma unroll
    for (int k = 0; k < IN_DIM; k++) {
#pragma unroll
        for (int off = 16; off > 0; off >>= 1)
            s[k] += __shfl_xor_sync(0xffffffffu, s[k], off);
    }

    float sx[IN_DIM];
#pragma unroll
    for (int k = 0; k < IN_DIM; k++) sx[k] = __ldg(&x[(size_t)node * IN_DIM + k]);

    int c0 = lane * 4;
    float4 v = *(const float4*)(brel + c0);
#pragma unroll
    for (int k = 0; k < IN_DIM; k++) {
        float4 wr = *(const float4*)(Wrel + k * HID + c0);
        float4 wo = *(const float4*)(Wroot + k * HID + c0);
        v.x = fmaf(s[k], wr.x, fmaf(sx[k], wo.x, v.x));
        v.y = fmaf(s[k], wr.y, fmaf(sx[k], wo.y, v.y));
        v.z = fmaf(s[k], wr.z, fmaf(sx[k], wo.z, v.z));
        v.w = fmaf(s[k], wr.w, fmaf(sx[k], wo.w, v.w));
    }
    v.x = fmaxf(v.x, 0.f); v.y = fmaxf(v.y, 0.f);
    v.z = fmaxf(v.z, 0.f); v.w = fmaxf(v.w, 0.f);

    unsigned h01, l01, h23, l23;
    split2(v.x, v.y, h01, l01);
    split2(v.z, v.w, h23, l23);
    *(uint2*)(g_cath + (size_t)node * 256 + 128 + c0) = make_uint2(h01, h23);
    *(uint2*)(g_catl + (size_t)node * 256 + 128 + c0) = make_uint2(l01, l23);
}

// ---------------- edge aggregation, warp per node (MLP=4) ----------------
__global__ void k_gather() {
    int node = (blockIdx.x * blockDim.x + threadIdx.x) >> 5;
    int lane = threadIdx.x & 31;
    if (node >= N_NODES) return;
    float a0 = 0.f, a1 = 0.f, a2 = 0.f, a3 = 0.f;
    int beg = g_rowptr[node], end = g_rowptr[node + 1];
    int j = beg;
    for (; j + 3 < end; j += 4) {
        int s0 = g_csr_src[j], s1 = g_csr_src[j + 1];
        int s2 = g_csr_src[j + 2], s3 = g_csr_src[j + 3];
        uint2 p0 = __ldg((const uint2*)(g_cath + (size_t)s0 * 256 + 128) + lane);
        uint2 p1 = __ldg((const uint2*)(g_cath + (size_t)s1 * 256 + 128) + lane);
        uint2 p2 = __ldg((const uint2*)(g_cath + (size_t)s2 * 256 + 128) + lane);
        uint2 p3 = __ldg((const uint2*)(g_cath + (size_t)s3 * 256 + 128) + lane);
        float2 f0 = __half22float2(*(__half2*)&p0.x);
        float2 f1 = __half22float2(*(__half2*)&p0.y);
        float2 g0 = __half22float2(*(__half2*)&p1.x);
        float2 g1 = __half22float2(*(__half2*)&p1.y);
        float2 q0 = __half22float2(*(__half2*)&p2.x);
        float2 q1 = __half22float2(*(__half2*)&p2.y);
        float2 r0 = __half22float2(*(__half2*)&p3.x);
        float2 r1 = __half22float2(*(__half2*)&p3.y);
        a0 += (f0.x + g0.x) + (q0.x + r0.x);
        a1 += (f0.y + g0.y) + (q0.y + r0.y);
        a2 += (f1.x + g1.x) + (q1.x + r1.x);
        a3 += (f1.y + g1.y) + (q1.y + r1.y);
    }
    for (; j < end; j++) {
        int s0 = g_csr_src[j];
        uint2 p0 = __ldg((const uint2*)(g_cath + (size_t)s0 * 256 + 128) + lane);
        float2 f0 = __half22float2(*(__half2*)&p0.x);
        float2 f1 = __half22float2(*(__half2*)&p0.y);
        a0 += f0.x; a1 += f0.y; a2 += f1.x; a3 += f1.y;
    }
    unsigned h01, l01, h23, l23;
    split2(a0, a1, h01, l01);
    split2(a2, a3, h23, l23);
    *((uint2*)(g_cath + (size_t)node * 256) + lane) = make_uint2(h01, h23);
    *((uint2*)(g_catl + (size_t)node * 256) + lane) = make_uint2(l01, l23);
}

// ---------------- split-fp16 tensor-core GEMM, cp.async pipelined ----------
// D = Ah*Wh + Ah*Wl + Al*Wh  (fp32 accumulate) ~ fp32-precision GEMM
__device__ __forceinline__ void mma16816(float* c, const unsigned* a,
                                         unsigned b0, unsigned b1) {
    asm volatile("mma.sync.aligned.m16n8k16.row.col.f32.f16.f16.f32 "
                 "{%0,%1,%2,%3}, {%4,%5,%6,%7}, {%8,%9}, {%0,%1,%2,%3};"
                 : "+f"(c[0]), "+f"(c[1]), "+f"(c[2]), "+f"(c[3])
                 : "r"(a[0]), "r"(a[1]), "r"(a[2]), "r"(a[3]), "r"(b0), "r"(b1));
}

#define LDMX4(dst, ptr)                                                          \
    { unsigned _ad = (unsigned)__cvta_generic_to_shared(ptr);                    \
      asm volatile("ldmatrix.sync.aligned.m8n8.x4.shared.b16 {%0,%1,%2,%3}, [%4];" \
                   : "=r"(dst[0]), "=r"(dst[1]), "=r"(dst[2]), "=r"(dst[3]) : "r"(_ad)); }
#define LDMX4T(dst, ptr)                                                         \
    { unsigned _ad = (unsigned)__cvta_generic_to_shared(ptr);                    \
      asm volatile("ldmatrix.sync.aligned.m8n8.x4.trans.shared.b16 {%0,%1,%2,%3}, [%4];" \
                   : "=r"(dst[0]), "=r"(dst[1]), "=r"(dst[2]), "=r"(dst[3]) : "r"(_ad)); }

__device__ __forceinline__ void cpa16(void* smem_dst, const void* gsrc) {
    unsigned d = (unsigned)__cvta_generic_to_shared(smem_dst);
    asm volatile("cp.async.cg.shared.global [%0], [%1], 16;" :: "r"(d), "l"(gsrc));
}
#define CP_COMMIT() asm volatile("cp.async.commit_group;")

// 128x128 block tile, 256 threads. Warp grid 4x2: warp tile 32 rows x 64 cols.
// K-chunk 16, 16 chunks over K=256, 2-stage cp.async double buffer.
// POOL==0: weights W1, relu, write h-slot hi/lo. POOL==1: weights W2, pool.
template <int POOL>
__global__ __launch_bounds__(256, 2)
void k_gemm(const float* __restrict__ bias, const int* __restrict__ batch) {
    __shared__ __half Ahs[2][128][24], Als[2][128][24];  // 128 x 16 (+8 pad)
    __shared__ __half Whs[2][16][136], Wls[2][16][136];  // 16 x 128 (+8 pad)

    const __half* __restrict__ WH = POOL ? g_W2hi : g_W1hi;
    const __half* __restrict__ WL = POOL ? g_W2lo : g_W1lo;

    const int tid = threadIdx.x;
    const int lane = tid & 31;
    const int w = tid >> 5;
    const int wr = w >> 1;            // 0..3 : rows wr*32 .. +32
    const int wc = w & 1;             // 0..1 : cols wc*64 .. +64
    const int row0 = blockIdx.x * 128;

    // per-thread cp.async coordinates (4 ops per chunk)
    const int a_r = tid >> 1, a_c = (tid & 1) * 8;        // A: 128 rows x 2 segs
    const int w_r = tid >> 4, w_c = (tid & 15) * 8;       // W: 16 rows x 16 segs

    float c[2][8][4];
#pragma unroll
    for (int i = 0; i < 2; i++)
#pragma unroll
        for (int t = 0; t < 8; t++)
#pragma unroll
            for (int q = 0; q < 4; q++) c[i][t][q] = 0.0f;

    const int a_co = (lane >> 4) << 3;                     // 0 or 8
    const int b_kr = (lane & 7) + (((lane >> 3) & 1) << 3);
    const int b_no = (lane >> 4) << 3;

    // prologue: load chunk 0 into buf 0
    {
        const int k0 = 0;
        cpa16(&Ahs[0][a_r][a_c], g_cath + (size_t)(row0 + a_r) * 256 + k0 + a_c);
        cpa16(&Als[0][a_r][a_c], g_catl + (size_t)(row0 + a_r) * 256 + k0 + a_c);
        cpa16(&Whs[0][w_r][w_c], WH + (size_t)(k0 + w_r) * HID + w_c);
        cpa16(&Wls[0][w_r][w_c], WL + (size_t)(k0 + w_r) * HID + w_c);
        CP_COMMIT();
    }

    for (int kc = 0; kc < 16; kc++) {
        const int buf = kc & 1;
        if (kc + 1 < 16) {
            const int nb = (kc + 1) & 1;
            const int k0 = (kc + 1) * 16;
            cpa16(&Ahs[nb][a_r][a_c], g_cath + (size_t)(row0 + a_r) * 256 + k0 + a_c);
            cpa16(&Als[nb][a_r][a_c], g_catl + (size_t)(row0 + a_r) * 256 + k0 + a_c);
            cpa16(&Whs[nb][w_r][w_c], WH + (size_t)(k0 + w_r) * HID + w_c);
            cpa16(&Wls[nb][w_r][w_c], WL + (size_t)(k0 + w_r) * HID + w_c);
            CP_COMMIT();
            asm volatile("cp.async.wait_group 1;");
        } else {
            asm volatile("cp.async.wait_group 0;");
        }
        __syncthreads();

        unsigned ah0[4], al0[4], ah1[4], al1[4];
        LDMX4(ah0, &Ahs[buf][wr * 32 + (lane & 15)][a_co]);
        LDMX4(al0, &Als[buf][wr * 32 + (lane & 15)][a_co]);
        LDMX4(ah1, &Ahs[buf][wr * 32 + 16 + (lane & 15)][a_co]);
        LDMX4(al1, &Als[buf][wr * 32 + 16 + (lane & 15)][a_co]);
#pragma unroll
        for (int t = 0; t < 4; t++) {
            unsigned bh[4], bl[4];
            LDMX4T(bh, &Whs[buf][b_kr][wc * 64 + t * 16 + b_no]);
            LDMX4T(bl, &Wls[buf][b_kr][wc * 64 + t * 16 + b_no]);
            mma16816(c[0][2 * t],     ah0, bh[0], bh[1]);
            mma16816(c[0][2 * t],     ah0, bl[0], bl[1]);
            mma16816(c[0][2 * t],     al0, bh[0], bh[1]);
            mma16816(c[0][2 * t + 1], ah0, bh[2], bh[3]);
            mma16816(c[0][2 * t + 1], ah0, bl[2], bl[3]);
            mma16816(c[0][2 * t + 1], al0, bh[2], bh[3]);
            mma16816(c[1][2 * t],     ah1, bh[0], bh[1]);
            mma16816(c[1][2 * t],     ah1, bl[0], bl[1]);
            mma16816(c[1][2 * t],     al1, bh[0], bh[1]);
            mma16816(c[1][2 * t + 1], ah1, bh[2], bh[3]);
            mma16816(c[1][2 * t + 1], ah1, bl[2], bl[3]);
            mma16816(c[1][2 * t + 1], al1, bh[2], bh[3]);
        }
        __syncthreads();
    }

    // epilogue
#pragma unroll
    for (int rf = 0; rf < 2; rf++) {
        int r0 = row0 + wr * 32 + rf * 16 + (lane >> 2);
        int r1 = r0 + 8;
        int g0 = 0, g1 = 0;
        if (POOL) {
            g0 = (r0 < N_NODES) ? batch[r0] : 0;
            g1 = (r1 < N_NODES) ? batch[r1] : 0;
        }
#pragma unroll
        for (int t2 = 0; t2 < 8; t2++) {
            int col = wc * 64 + t2 * 8 + (lane & 3) * 2;
            float bv0 = bias[col], bv1 = bias[col + 1];
            float v00 = c[rf][t2][0] + bv0, v01 = c[rf][t2][1] + bv1;
            float v10 = c[rf][t2][2] + bv0, v11 = c[rf][t2][3] + bv1;
            if (!POOL) {
                v00 = fmaxf(v00, 0.f); v01 = fmaxf(v01, 0.f);
                v10 = fmaxf(v10, 0.f); v11 = fmaxf(v11, 0.f);
                unsigned h0v, l0v, h1v, l1v;
                split2(v00, v01, h0v, l0v);
                split2(v10, v11, h1v, l1v);
                *(unsigned*)(g_cath + (size_t)r0 * 256 + 128 + col) = h0v;
                *(unsigned*)(g_catl + (size_t)r0 * 256 + 128 + col) = l0v;
                *(unsigned*)(g_cath + (size_t)r1 * 256 + 128 + col) = h1v;
                *(unsigned*)(g_catl + (size_t)r1 * 256 + 128 + col) = l1v;
            } else {
                if (r0 < N_NODES) {
                    atomicAdd(&g_pooled[(size_t)g0 * HID + col], v00);
                    atomicAdd(&g_pooled[(size_t)g0 * HID + col + 1], v01);
                }
                if (r1 < N_NODES) {
                    atomicAdd(&g_pooled[(size_t)g1 * HID + col], v10);
                    atomicAdd(&g_pooled[(size_t)g1 * HID + col + 1], v11);
                }
            }
        }
    }
}

// ---------------- final: mean pool -> linear -> sigmoid ----------------
__global__ void k_final(const float* __restrict__ Wlin, const float* __restrict__ blin,
                        float* __restrict__ out) {
    int g = blockIdx.x;
    int t = threadIdx.x;              // 128
    float cnt = fmaxf((float)g_cnt[g], 1.0f);
    float v = g_pooled[(size_t)g * HID + t] * (1.0f / cnt) * Wlin[t];
#pragma unroll
    for (int off = 16; off > 0; off >>= 1)
        v += __shfl_xor_sync(0xffffffffu, v, off);
    __shared__ float ws[4];
    if ((t & 31) == 0) ws[t >> 5] = v;
    __syncthreads();
    if (t == 0) {
        float s = ws[0] + ws[1] + ws[2] + ws[3] + blin[0];
        out[g] = 1.0f / (1.0f + expf(-s));
    }
}

// ---------------- launch ----------------
extern "C" void kernel_launch(void* const* d_in, const int* in_sizes, int n_in,
                              void* d_out, int out_size) {
    const float* x      = (const float*)d_in[0];
    const int*   ei     = (const int*)d_in[1];
    const int*   batch  = (const int*)d_in[2];
    const float* Wrel0  = (const float*)d_in[3];
    const float* brel0  = (const float*)d_in[4];
    const float* Wroot0 = (const float*)d_in[5];
    const float* Wrel1  = (const float*)d_in[6];
    const float* brel1  = (const float*)d_in[7];
    const float* Wroot1 = (const float*)d_in[8];
    const float* Wrel2  = (const float*)d_in[9];
    const float* brel2  = (const float*)d_in[10];
    const float* Wroot2 = (const float*)d_in[11];
    const float* Wlin   = (const float*)d_in[12];
    const float* blin   = (const float*)d_in[13];
    float* out = (float*)d_out;

    k_init<<<256, 256>>>(Wrel1, Wroot1, Wrel2, Wroot2);
    k_histcnt<<<(N_EDGES + 255) / 256, 256>>>(ei, batch);
    k_scanA<<<NB, 256>>>();
    k_scanC<<<NB, 256>>>();
    k_scatter<<<(N_EDGES + 255) / 256, 256>>>(ei);

    // layer 0 (fused agg + linear + relu) -> h @ col 128
    k_l0<<<(N_NODES * 32 + 255) / 256, 256>>>(x, Wrel0, brel0, Wroot0);

    // layer 1
    k_gather<<<(N_NODES * 32 + 255) / 256, 256>>>();
    k_gemm<0><<<N_PAD / 128, 256>>>(brel1, batch);

    // layer 2 (+ fused pooling accumulate)
    k_gather<<<(N_NODES * 32 + 255) / 256, 256>>>();
    k_gemm<1><<<N_PAD / 128, 256>>>(brel2, batch);

    // head
    k_final<<<NUM_GRAPHS, HID>>>(Wlin, blin, out);
}